// round 6
// baseline (speedup 1.0000x reference)
#include <cuda_runtime.h>

#define N_NODES 10000
#define N_EDGES 320000
#define QUADS (N_EDGES / 4)
#define NB 296
#define NT 1024
#define NTHR (NB * NT)
#define DCHUNK 34
#define NCHUNK ((N_NODES + DCHUNK - 1) / DCHUNK)  // 295
#define BM_WORDS 320

// Packed probe-vector storage (struct-of-slots per tree level).
__device__ float2 g_CL1[N_NODES];   // {R1, R2}
__device__ float4 g_CL2[N_NODES];   // {R3, R5, R4, R6}
__device__ float4 g_CL3a[N_NODES];  // {R7, R10, R11, pad}
__device__ float4 g_CL3b[N_NODES];  // {R8, R9, R12, pad}
__device__ float4 g_CL4[N_NODES];   // {R13, R15, R14, R16}
__device__ unsigned g_bm1[BM_WORDS];
__device__ unsigned g_bm2[BM_WORDS];
__device__ float g_D[17][4][64];
__device__ float g_T[5][4][128];
__device__ float g_sig[5];
__device__ int g_count;
__device__ volatile int g_gen;

__constant__ int c_VEC_ID[5][5] = {
    {0, 1, 3, 2, 6},
    {1, 3, 7, 4, 9},
    {3, 7, 13, 8, 14},
    {2, 5, 10, 6, 12},
    {6, 11, 15, 12, 16}};
__constant__ int c_SVID[16] = {1, 2, 3, 5, 4, 6, 7, 10, 11, 8, 9, 12, 13, 15, 14, 16};

__device__ __forceinline__ void red2(float* p, float a, float b) {
    asm volatile("red.global.add.v2.f32 [%0], {%1,%2};" :: "l"(p), "f"(a), "f"(b) : "memory");
}
__device__ __forceinline__ void red4(float* p, float a, float b, float c, float d) {
    asm volatile("red.global.add.v4.f32 [%0], {%1,%2,%3,%4};"
                 :: "l"(p), "f"(a), "f"(b), "f"(c), "f"(d) : "memory");
}
__device__ __forceinline__ float ldcg1(const float* p) {
    float r; asm volatile("ld.global.cg.f32 %0,[%1];" : "=f"(r) : "l"(p)); return r;
}
__device__ __forceinline__ unsigned ldcg1u(const unsigned* p) {
    unsigned r; asm volatile("ld.global.cg.u32 %0,[%1];" : "=r"(r) : "l"(p)); return r;
}
__device__ __forceinline__ float2 ldcg2(const float2* p) {
    float2 r; asm volatile("ld.global.cg.v2.f32 {%0,%1},[%2];"
                           : "=f"(r.x), "=f"(r.y) : "l"(p)); return r;
}
__device__ __forceinline__ float4 ldcg4(const float4* p) {
    float4 r; asm volatile("ld.global.cg.v4.f32 {%0,%1,%2,%3},[%4];"
                           : "=f"(r.x), "=f"(r.y), "=f"(r.z), "=f"(r.w) : "l"(p)); return r;
}

__device__ __forceinline__ void barrier_arrive(int target) {
    __syncthreads();
    if (threadIdx.x == 0) {
        __threadfence();
        int gen = g_gen;
        if (atomicAdd(&g_count, 1) == target - 1) {
            g_count = 0;
            __threadfence();
            g_gen = gen + 1;
        }
    }
}
__device__ __forceinline__ void barrier_wait(int target) {
    __syncthreads();
    if (threadIdx.x == 0) {
        __threadfence();
        int gen = g_gen;
        if (atomicAdd(&g_count, 1) == target - 1) {
            g_count = 0;
            __threadfence();
            g_gen = gen + 1;
        } else {
            while (g_gen == gen) __nanosleep(64);
        }
    }
    __syncthreads();
}

__global__ void __launch_bounds__(NT, 2)
fused_kernel(const int* __restrict__ eidx, const float* __restrict__ evals,
             const float* __restrict__ x,
             const float* __restrict__ W1, const float* __restrict__ b1,
             const float* __restrict__ W2, const float* __restrict__ b2,
             float* __restrict__ out) {
    __shared__ float Rs[16 * DCHUNK];     // 2.2 KB
    __shared__ unsigned sbm[BM_WORDS];    // 1.25 KB
    __shared__ float4 part[12][32];       // 6 KB

    const int tid = threadIdx.x;
    const int gtid = blockIdx.x * NT + tid;
    const float4 z4 = make_float4(0.f, 0.f, 0.f, 0.f);

    // ---- P0: zero CL1, bitmaps, D, T, sig ----
    for (int i = gtid; i < N_NODES; i += NTHR) g_CL1[i] = make_float2(0.f, 0.f);
    for (int i = gtid; i < 17 * 4 * 64; i += NTHR) (&g_D[0][0][0])[i] = 0.f;
    for (int i = gtid; i < 5 * 4 * 128; i += NTHR) (&g_T[0][0][0])[i] = 0.f;
    if (gtid < BM_WORDS) { g_bm1[gtid] = 0u; g_bm2[gtid] = 0u; }
    if (gtid < 5) g_sig[gtid] = 0.f;
    barrier_wait(NB);

    // ---- P1: lvl1 (parent = e_0) + build bm1 + zero CL2 ----
    for (int i = gtid; i < N_NODES; i += NTHR) g_CL2[i] = z4;
    for (int q = gtid; q < 2 * QUADS; q += NTHR) {
        int g = q >= QUADS;
        int j = q - g * QUADS;
        const int* eb = eidx + (size_t)g * 2 * N_EDGES;
        int4 r = __ldg((const int4*)eb + j);
        if (r.x == 0 || r.y == 0 || r.z == 0 || r.w == 0) {
            const int ri[4] = {r.x, r.y, r.z, r.w};
            float* base = (float*)g_CL1 + g;
#pragma unroll
            for (int i = 0; i < 4; i++)
                if (ri[i] == 0) {
                    int c = __ldg(eb + N_EDGES + j * 4 + i);
                    float v = __ldg(evals + (size_t)g * N_EDGES + j * 4 + i);
                    atomicAdd(base + c * 2, v);
                    atomicOr(&g_bm1[c >> 5], 1u << (c & 31));
                }
        }
    }
    barrier_wait(NB);

    // ---- P2: lvl2 (bm1-filtered, scalar c/v) + build bm2 + zero CL3 ----
    if (tid < BM_WORDS) sbm[tid] = ldcg1u(&g_bm1[tid]);
    __syncthreads();
    for (int i = gtid; i < N_NODES; i += NTHR) { g_CL3a[i] = z4; g_CL3b[i] = z4; }
    for (int q = gtid; q < 2 * QUADS; q += NTHR) {
        int g = q >= QUADS;
        int j = q - g * QUADS;
        const int* eb = eidx + (size_t)g * 2 * N_EDGES;
        int4 r = __ldg((const int4*)eb + j);
        const int ri[4] = {r.x, r.y, r.z, r.w};
        unsigned any = 0;
#pragma unroll
        for (int i = 0; i < 4; i++)
            any |= (sbm[ri[i] >> 5] >> (ri[i] & 31)) & 1u ? (1u << i) : 0u;
        if (!any) continue;
        float* base = (float*)g_CL2 + 2 * g;
#pragma unroll
        for (int i = 0; i < 4; i++)
            if (any & (1u << i)) {
                float2 qv = ldcg2(g_CL1 + ri[i]);
                if ((qv.x != 0.f) | (qv.y != 0.f)) {
                    int c = __ldg(eb + N_EDGES + j * 4 + i);
                    float v = __ldg(evals + (size_t)g * N_EDGES + j * 4 + i);
                    red2(base + c * 4, v * qv.x, v * qv.y);
                    atomicOr(&g_bm2[c >> 5], 1u << (c & 31));
                }
            }
    }
    barrier_wait(NB);

    // ---- P3: lvl3 (bm2-filtered, scalar c/v) + zero CL4 ----
    if (tid < BM_WORDS) sbm[tid] = ldcg1u(&g_bm2[tid]);
    __syncthreads();
    for (int i = gtid; i < N_NODES; i += NTHR) g_CL4[i] = z4;
    for (int q = gtid; q < 2 * QUADS; q += NTHR) {
        int g = q >= QUADS;
        int j = q - g * QUADS;
        const int* eb = eidx + (size_t)g * 2 * N_EDGES;
        int4 r = __ldg((const int4*)eb + j);
        const int ri[4] = {r.x, r.y, r.z, r.w};
        unsigned any = 0;
#pragma unroll
        for (int i = 0; i < 4; i++)
            any |= (sbm[ri[i] >> 5] >> (ri[i] & 31)) & 1u ? (1u << i) : 0u;
        if (!any) continue;
        float4* dst = g ? g_CL3b : g_CL3a;
#pragma unroll
        for (int i = 0; i < 4; i++)
            if (any & (1u << i)) {
                float4 qv = ldcg4(g_CL2 + ri[i]);
                float p0 = qv.x;
                float p1 = g ? qv.z : qv.y;
                float p2 = qv.w;
                if ((p0 != 0.f) | (p1 != 0.f) | (p2 != 0.f)) {
                    int c = __ldg(eb + N_EDGES + j * 4 + i);
                    float v = __ldg(evals + (size_t)g * N_EDGES + j * 4 + i);
                    red4((float*)&dst[c], v * p0, v * p1, v * p2, 0.f);
                }
            }
    }
    barrier_wait(NB);

    // ---- P4: lvl4 (dense; 2+2 gather pipeline to cap reg pressure) ----
    for (int q = gtid; q < 2 * QUADS; q += NTHR) {
        int g = q >= QUADS;
        int j = q - g * QUADS;
        const int* eb = eidx + (size_t)g * 2 * N_EDGES;
        const float4* src = g ? g_CL3b : g_CL3a;
        int4 r = __ldg((const int4*)eb + j);
        int4 c = __ldg((const int4*)(eb + N_EDGES) + j);
        float4 v = __ldg((const float4*)(evals + (size_t)g * N_EDGES) + j);
        float* base = (float*)g_CL4 + 2 * g;
        {
            float4 q0 = ldcg4(src + r.x), q1 = ldcg4(src + r.y);
            if ((q0.x != 0.f) | (q0.z != 0.f)) red2(base + c.x * 4, v.x * q0.x, v.x * q0.z);
            if ((q1.x != 0.f) | (q1.z != 0.f)) red2(base + c.y * 4, v.y * q1.x, v.y * q1.z);
        }
        {
            float4 q2 = ldcg4(src + r.z), q3 = ldcg4(src + r.w);
            if ((q2.x != 0.f) | (q2.z != 0.f)) red2(base + c.z * 4, v.z * q2.x, v.z * q2.z);
            if ((q3.x != 0.f) | (q3.z != 0.f)) red2(base + c.w * 4, v.w * q3.x, v.w * q3.z);
        }
    }
    barrier_wait(NB);

    // ---- P5: dot  D[v][b][f] = sum_n R[v][n] x[b][n][f]; sigma folded ----
    if (blockIdx.x < NCHUNK) {
        int n0 = blockIdx.x * DCHUNK;
        int lim = min(DCHUNK, N_NODES - n0);
        if (tid < DCHUNK) {
            int gn = n0 + tid;
            bool ok = gn < N_NODES;
            float2 a = ok ? ldcg2(g_CL1 + gn) : make_float2(0.f, 0.f);
            float4 c2 = ok ? ldcg4(g_CL2 + gn) : z4;
            float4 c3a = ok ? ldcg4(g_CL3a + gn) : z4;
            float4 c3b = ok ? ldcg4(g_CL3b + gn) : z4;
            float4 c4 = ok ? ldcg4(g_CL4 + gn) : z4;
            Rs[0 * DCHUNK + tid] = a.x;   Rs[1 * DCHUNK + tid] = a.y;
            Rs[2 * DCHUNK + tid] = c2.x;  Rs[3 * DCHUNK + tid] = c2.y;
            Rs[4 * DCHUNK + tid] = c2.z;  Rs[5 * DCHUNK + tid] = c2.w;
            Rs[6 * DCHUNK + tid] = c3a.x; Rs[7 * DCHUNK + tid] = c3a.y;
            Rs[8 * DCHUNK + tid] = c3a.z;
            Rs[9 * DCHUNK + tid] = c3b.x; Rs[10 * DCHUNK + tid] = c3b.y;
            Rs[11 * DCHUNK + tid] = c3b.z;
            Rs[12 * DCHUNK + tid] = c4.x; Rs[13 * DCHUNK + tid] = c4.y;
            Rs[14 * DCHUNK + tid] = c4.z; Rs[15 * DCHUNK + tid] = c4.w;
        }
        __syncthreads();
        if (tid < 128) {  // sigma: vids {1,3,2,6} = slots {0,2,1,5}
            const int slots[4] = {0, 2, 1, 5};
            int vi = tid >> 5, lane = tid & 31;
            float s = 0.f;
            for (int n = lane; n < DCHUNK; n += 32) s += Rs[slots[vi] * DCHUNK + n];
#pragma unroll
            for (int off = 16; off; off >>= 1) s += __shfl_down_sync(0xffffffffu, s, off);
            if (lane == 0) atomicAdd(&g_sig[vi + 1], s);
        }
        int f = tid & 63;
        int bb = (tid >> 6) & 3;
        int vg = tid >> 8;
        float acc0 = 0.f, acc1 = 0.f, acc2 = 0.f, acc3 = 0.f;
        const float* xb = x + ((size_t)bb * N_NODES + n0) * 64 + f;
        const float* rsv = Rs + vg * 4 * DCHUNK;
        for (int nn = 0; nn < lim; nn++) {
            float xv = __ldg(xb + (size_t)nn * 64);
            acc0 += rsv[0 * DCHUNK + nn] * xv;
            acc1 += rsv[1 * DCHUNK + nn] * xv;
            acc2 += rsv[2 * DCHUNK + nn] * xv;
            acc3 += rsv[3 * DCHUNK + nn] * xv;
        }
        atomicAdd(&g_D[c_SVID[vg * 4 + 0]][bb][f], acc0);
        atomicAdd(&g_D[c_SVID[vg * 4 + 1]][bb][f], acc1);
        atomicAdd(&g_D[c_SVID[vg * 4 + 2]][bb][f], acc2);
        atomicAdd(&g_D[c_SVID[vg * 4 + 3]][bb][f], acc3);
    }
    if (blockIdx.x >= 124) { barrier_arrive(NB); return; }
    barrier_wait(NB);

    // ---- P6a: T partials (blocks 0..119: (b,si,pc)); 120..123 init out=b2 ----
    {
        int id = blockIdx.x;
        int lane = tid & 31, w = tid >> 5;
        if (id < 120) {
            int b = id & 3, si = (id >> 2) % 5, pc = id / 20;
            int e = pc / 3, k = pc % 3;
            int pi = (k == 0) ? 0 : (e * 2 + k);
            int vid = c_VEC_ID[si][pi];
            const float* Dp = vid ? &g_D[vid][b][0] : (x + (size_t)b * N_NODES * 64);
            const float* Wp = W1 + (size_t)pc * 64 * 128;
            if (w < 12) {
                float4 acc = z4;
                for (int f = w; f < 64; f += 12) {
                    float d = vid ? ldcg1(Dp + f) : __ldg(Dp + f);
                    float4 wv = __ldg((const float4*)(Wp + (size_t)f * 128) + lane);
                    acc.x += d * wv.x; acc.y += d * wv.y;
                    acc.z += d * wv.z; acc.w += d * wv.w;
                }
                part[w][lane] = acc;
            }
            __syncthreads();
            if (w == 0) {
                float4 o = z4;
#pragma unroll
                for (int i = 0; i < 12; i++) {
                    float4 a = part[i][lane];
                    o.x += a.x; o.y += a.y; o.z += a.z; o.w += a.w;
                }
                float* tp = &g_T[si][b][lane * 4];
                atomicAdd(tp + 0, o.x); atomicAdd(tp + 1, o.y);
                atomicAdd(tp + 2, o.z); atomicAdd(tp + 3, o.w);
            }
        } else {
            int b = id - 120;
            if (tid < 32)
                ((float4*)(out + (size_t)b * 128))[tid] = __ldg((const float4*)b2 + tid);
        }
    }
    if (blockIdx.x >= 24) { barrier_arrive(124); return; }
    barrier_wait(124);

    // ---- P6b: out partials (blocks 0..23: (b,pc)) ----
    {
        int id = blockIdx.x;
        int b = id & 3, pc = id >> 2;
        int e = pc / 3, k = pc % 3;
        int si = (k == 0) ? 0 : (e * 2 + k);
        float sg = (si == 0) ? 1.0f : ldcg1(&g_sig[si]);
        int lane = tid & 31, w = tid >> 5;
        const float* Tp = &g_T[si][b][0];
        const float* Wp = W2 + (size_t)pc * 128 * 128;
        if (w < 12) {
            float4 acc = z4;
            for (int f = w; f < 128; f += 12) {
                float t = ldcg1(Tp + f) + sg * __ldg(b1 + f);
                float4 wv = __ldg((const float4*)(Wp + (size_t)f * 128) + lane);
                acc.x += t * wv.x; acc.y += t * wv.y;
                acc.z += t * wv.z; acc.w += t * wv.w;
            }
            part[w][lane] = acc;
        }
        __syncthreads();
        if (w == 0) {
            float4 o = z4;
#pragma unroll
            for (int i = 0; i < 12; i++) {
                float4 a = part[i][lane];
                o.x += a.x; o.y += a.y; o.z += a.z; o.w += a.w;
            }
            float* op = out + (size_t)b * 128 + lane * 4;
            atomicAdd(op + 0, o.x); atomicAdd(op + 1, o.y);
            atomicAdd(op + 2, o.z); atomicAdd(op + 3, o.w);
        }
    }
}

extern "C" void kernel_launch(void* const* d_in, const int* in_sizes, int n_in,
                              void* d_out, int out_size) {
    const float* x = nullptr;
    const int* eidx = nullptr;
    const float* evals = nullptr;
    const float *W1 = nullptr, *b1 = nullptr, *W2 = nullptr, *b2 = nullptr;
    for (int i = 0; i < n_in; i++) {
        switch (in_sizes[i]) {
            case 2560000: x = (const float*)d_in[i]; break;
            case 1280000: eidx = (const int*)d_in[i]; break;
            case 640000:  evals = (const float*)d_in[i]; break;
            case 49152:   W1 = (const float*)d_in[i]; break;
            case 98304:   W2 = (const float*)d_in[i]; break;
            case 128:
                if (!b1) b1 = (const float*)d_in[i];
                else b2 = (const float*)d_in[i];
                break;
        }
    }
    float* out = (float*)d_out;
    fused_kernel<<<NB, NT>>>(eidx, evals, x, W1, b1, W2, b2, out);
}